// round 13
// baseline (speedup 1.0000x reference)
#include <cuda_runtime.h>
#include <cuda_bf16.h>
#include <math.h>
#include <stdint.h>

#define B_SZ    2
#define S_LEN   2048
#define D_MODEL 1024
#define NHEAD   16
#define HDIM    64
#define M_ROWS  (B_SZ * S_LEN)   // 4096
#define WSZ     (D_MODEL * D_MODEL)   // 1M
#define HS      (B_SZ * NHEAD)   // 32 heads total

// ---------------- scratch (device-side only) ----------------
__device__ float2 g_rope[S_LEN * 32];
__device__ __nv_bfloat16 g_xhi[M_ROWS * D_MODEL];
__device__ __nv_bfloat16 g_xlo[M_ROWS * D_MODEL];
__device__ __nv_bfloat16 g_whi[4 * WSZ];
__device__ __nv_bfloat16 g_wlo[4 * WSZ];
__device__ __nv_bfloat16 g_ahi[M_ROWS * D_MODEL];
__device__ __nv_bfloat16 g_alo[M_ROWS * D_MODEL];
__device__ __nv_bfloat16 g_qhi[HS * S_LEN * HDIM];
__device__ __nv_bfloat16 g_qlo[HS * S_LEN * HDIM];
__device__ __nv_bfloat16 g_khi[HS * S_LEN * HDIM];
__device__ __nv_bfloat16 g_klo[HS * S_LEN * HDIM];
__device__ __nv_bfloat16 g_vthi[HS * HDIM * S_LEN];
__device__ __nv_bfloat16 g_vtlo[HS * HDIM * S_LEN];

// ================= helpers =================
__device__ __forceinline__ uint32_t smem_u32(const void* p) {
    uint32_t a;
    asm("{ .reg .u64 t; cvta.to.shared.u64 t, %1; cvt.u32.u64 %0, t; }" : "=r"(a) : "l"(p));
    return a;
}
__device__ __forceinline__ void ldsm_x4(uint32_t& r0, uint32_t& r1, uint32_t& r2, uint32_t& r3,
                                        uint32_t addr) {
    asm volatile("ldmatrix.sync.aligned.m8n8.x4.shared.b16 {%0,%1,%2,%3}, [%4];"
                 : "=r"(r0), "=r"(r1), "=r"(r2), "=r"(r3) : "r"(addr));
}
__device__ __forceinline__ void mma16816(float* c, const uint32_t* a, const uint32_t* b) {
    asm volatile(
        "mma.sync.aligned.m16n8k16.row.col.f32.bf16.bf16.f32 "
        "{%0,%1,%2,%3}, {%4,%5,%6,%7}, {%8,%9}, {%0,%1,%2,%3};"
        : "+f"(c[0]), "+f"(c[1]), "+f"(c[2]), "+f"(c[3])
        : "r"(a[0]), "r"(a[1]), "r"(a[2]), "r"(a[3]), "r"(b[0]), "r"(b[1]));
}
__device__ __forceinline__ void cp16(uint32_t dst, const void* src) {
    asm volatile("cp.async.cg.shared.global [%0], [%1], 16;" :: "r"(dst), "l"(src));
}
#define CP_COMMIT() asm volatile("cp.async.commit_group;" ::: "memory")
#define CP_WAIT1()  asm volatile("cp.async.wait_group 1;" ::: "memory")

__device__ __forceinline__ uint32_t ldsm_addr_s(uint32_t base, int row0, int col0,
                                                int lane, int stride) {
    int sub = lane >> 3, r8 = lane & 7;
    int row = row0 + r8 + (sub & 1) * 8;
    int col = col0 + (sub >> 1) * 8;
    return base + (uint32_t)(row * stride + col) * 2;
}
__device__ __forceinline__ void bsplit(float v, __nv_bfloat16& hi, __nv_bfloat16& lo) {
    hi = __float2bfloat16(v);
    lo = __float2bfloat16(v - __bfloat162float(hi));
}

// ============== pipelined tensor GEMM mainloop =============================
#define TSTR 40
#define STG  (128 * TSTR)                 // elems per buffer
#define GEMM_SMEM (2 * 4 * STG * 2)       // 81920 B
#define CSTR 129                          // fp32 epilogue tile stride

__device__ __forceinline__ void gemm_stage_load(__nv_bfloat16* st,
                                                const __nv_bfloat16* Ahi,
                                                const __nv_bfloat16* Alo,
                                                const __nv_bfloat16* Bhi,
                                                const __nv_bfloat16* Blo,
                                                int m0, int n0, int kb, int tid) {
    uint32_t b0 = smem_u32(st);
#pragma unroll
    for (int i = 0; i < 2; i++) {
        int li  = tid + i * 256;
        int row = li >> 2;
        int c8  = (li & 3) * 8;
        uint32_t so = (uint32_t)(row * TSTR + c8) * 2;
        size_t ga = (size_t)(m0 + row) * D_MODEL + kb + c8;
        size_t gb = (size_t)(n0 + row) * D_MODEL + kb + c8;
        cp16(b0 + so,           Ahi + ga);
        cp16(b0 + STG * 2 + so, Alo + ga);
        cp16(b0 + STG * 4 + so, Bhi + gb);
        cp16(b0 + STG * 6 + so, Blo + gb);
    }
}

__device__ __forceinline__ void tgemm_mainloop(const __nv_bfloat16* __restrict__ Ahi,
                                               const __nv_bfloat16* __restrict__ Alo,
                                               const __nv_bfloat16* __restrict__ Bhi,
                                               const __nv_bfloat16* __restrict__ Blo,
                                               int m0, int n0,
                                               float (&acc)[4][4][4],
                                               __nv_bfloat16* dsm) {
    const int tid  = threadIdx.x;
    const int lane = tid & 31;
    const int wid  = tid >> 5;
    const int wm   = (wid & 1) * 64;
    const int wn   = (wid >> 1) * 32;

#pragma unroll
    for (int i = 0; i < 4; i++)
#pragma unroll
        for (int j = 0; j < 4; j++)
#pragma unroll
            for (int r = 0; r < 4; r++) acc[i][j][r] = 0.f;

    gemm_stage_load(dsm, Ahi, Alo, Bhi, Blo, m0, n0, 0, tid);
    CP_COMMIT();

    for (int ch = 0; ch < 32; ch++) {
        if (ch < 31)
            gemm_stage_load(dsm + ((ch + 1) & 1) * 4 * STG, Ahi, Alo, Bhi, Blo,
                            m0, n0, (ch + 1) * 32, tid);
        CP_COMMIT();
        CP_WAIT1();
        __syncthreads();

        uint32_t b0  = smem_u32(dsm + (ch & 1) * 4 * STG);
        uint32_t bAh = b0, bAl = b0 + STG * 2, bBh = b0 + STG * 4, bBl = b0 + STG * 6;

#pragma unroll
        for (int ks = 0; ks < 2; ks++) {
            const int kk = ks * 16;
            uint32_t afh[4][4], afl[4][4];
#pragma unroll
            for (int ma = 0; ma < 4; ma++) {
                ldsm_x4(afh[ma][0], afh[ma][1], afh[ma][2], afh[ma][3],
                        ldsm_addr_s(bAh, wm + ma * 16, kk, lane, TSTR));
                ldsm_x4(afl[ma][0], afl[ma][1], afl[ma][2], afl[ma][3],
                        ldsm_addr_s(bAl, wm + ma * 16, kk, lane, TSTR));
            }
            uint32_t bfh[4][2], bfl[4][2];
#pragma unroll
            for (int p = 0; p < 2; p++) {
                uint32_t r0, r1, r2, r3;
                ldsm_x4(r0, r1, r2, r3, ldsm_addr_s(bBh, wn + p * 16, kk, lane, TSTR));
                bfh[p * 2 + 0][0] = r0; bfh[p * 2 + 0][1] = r2;
                bfh[p * 2 + 1][0] = r1; bfh[p * 2 + 1][1] = r3;
                ldsm_x4(r0, r1, r2, r3, ldsm_addr_s(bBl, wn + p * 16, kk, lane, TSTR));
                bfl[p * 2 + 0][0] = r0; bfl[p * 2 + 0][1] = r2;
                bfl[p * 2 + 1][0] = r1; bfl[p * 2 + 1][1] = r3;
            }
#pragma unroll
            for (int ma = 0; ma < 4; ma++)
#pragma unroll
                for (int na = 0; na < 4; na++) {
                    mma16816(acc[ma][na], afh[ma], bfh[na]);
                    mma16816(acc[ma][na], afh[ma], bfl[na]);
                    mma16816(acc[ma][na], afl[ma], bfh[na]);
                }
        }
        __syncthreads();
    }
}

// store accumulators into fp32 smem tile [128][CSTR]
__device__ __forceinline__ void acc_to_smem(float (&acc)[4][4][4], float* ct) {
    const int lane = threadIdx.x & 31;
    const int wid  = threadIdx.x >> 5;
    const int wm   = (wid & 1) * 64;
    const int wn   = (wid >> 1) * 32;
#pragma unroll
    for (int ma = 0; ma < 4; ma++)
#pragma unroll
        for (int na = 0; na < 4; na++) {
            int r = wm + ma * 16 + (lane >> 2);
            int c = wn + na * 8 + (lane & 3) * 2;
            ct[r * CSTR + c]           = acc[ma][na][0];
            ct[r * CSTR + c + 1]       = acc[ma][na][1];
            ct[(r + 8) * CSTR + c]     = acc[ma][na][2];
            ct[(r + 8) * CSTR + c + 1] = acc[ma][na][3];
        }
}

// QKV GEMM with fused epilogue: rope+split+relayout (q,k) / transpose+split (v)
__global__ __launch_bounds__(256) void tgemm_qkv_kernel() {
    extern __shared__ __nv_bfloat16 dsm[];
    const int z  = blockIdx.z;
    const int m0 = blockIdx.y * 128;
    const int n0 = blockIdx.x * 128;
    const int tid = threadIdx.x;

    float acc[4][4][4];
    tgemm_mainloop(g_xhi, g_xlo, g_whi + (size_t)z * WSZ, g_wlo + (size_t)z * WSZ,
                   m0, n0, acc, dsm);

    float* ct = (float*)dsm;
    acc_to_smem(acc, ct);
    __syncthreads();

    const int b  = m0 >> 11;           // batch of this row block
    const int s0 = m0 & (S_LEN - 1);
    const int h0 = n0 >> 6;            // first head in this col block

    if (z < 2) {
        __nv_bfloat16* Dhi = z ? g_khi : g_qhi;
        __nv_bfloat16* Dlo = z ? g_klo : g_qlo;
        // 128 rows x 2 heads x 32 pair-dims = 8192 pairs
#pragma unroll
        for (int i = 0; i < 32; i++) {
            int idx = tid + i * 256;
            int d  = idx & 31;
            int hh = (idx >> 5) & 1;
            int r  = idx >> 6;
            int s  = s0 + r;
            float2 cs = g_rope[s * 32 + d];
            float v1 = ct[r * CSTR + hh * 64 + d];
            float v2 = ct[r * CSTR + hh * 64 + d + 32];
            float qa = v1 * cs.x - v2 * cs.y;
            float qb = v2 * cs.x + v1 * cs.y;
            size_t dst = ((size_t)(b * NHEAD + h0 + hh) * S_LEN + s) * HDIM + d;
            __nv_bfloat16 hi, lo;
            bsplit(qa, hi, lo); Dhi[dst]      = hi; Dlo[dst]      = lo;
            bsplit(qb, hi, lo); Dhi[dst + 32] = hi; Dlo[dst + 32] = lo;
        }
    } else {
        // v: transpose to [bh][d][s] with split; 128 cols x 128 rows
#pragma unroll
        for (int i = 0; i < 64; i++) {
            int idx = tid + i * 256;        // 0..16383
            int sl = idx & 127;
            int c  = idx >> 7;              // 0..127
            int h  = c >> 6, d = c & 63;
            float v = ct[sl * CSTR + c];
            size_t dst = ((size_t)((b * NHEAD + h0 + h) * HDIM + d)) * S_LEN + s0 + sl;
            __nv_bfloat16 hi, lo;
            bsplit(v, hi, lo);
            g_vthi[dst] = hi; g_vtlo[dst] = lo;
        }
    }
}

__global__ __launch_bounds__(256) void tgemm_o_kernel(float* __restrict__ C) {
    extern __shared__ __nv_bfloat16 dsm[];
    const int m0 = blockIdx.y * 128;
    const int n0 = blockIdx.x * 128;
    const int lane = threadIdx.x & 31;
    const int wid  = threadIdx.x >> 5;
    const int wm   = (wid & 1) * 64;
    const int wn   = (wid >> 1) * 32;

    float acc[4][4][4];
    tgemm_mainloop(g_ahi, g_alo, g_whi + (size_t)3 * WSZ, g_wlo + (size_t)3 * WSZ,
                   m0, n0, acc, dsm);

#pragma unroll
    for (int ma = 0; ma < 4; ma++)
#pragma unroll
        for (int na = 0; na < 4; na++) {
            int r = m0 + wm + ma * 16 + (lane >> 2);
            int c = n0 + wn + na * 8 + (lane & 3) * 2;
            *(float2*)(C + (size_t)r * D_MODEL + c)       = make_float2(acc[ma][na][0], acc[ma][na][1]);
            *(float2*)(C + (size_t)(r + 8) * D_MODEL + c) = make_float2(acc[ma][na][2], acc[ma][na][3]);
        }
}

// ================= bf16-split conversions =================
__global__ __launch_bounds__(256) void convert_x_kernel(const float* __restrict__ x) {
    int i = blockIdx.x * 256 + threadIdx.x;
    __nv_bfloat16 hi, lo;
    bsplit(x[i], hi, lo);
    g_xhi[i] = hi; g_xlo[i] = lo;
}
__global__ __launch_bounds__(256) void convert_w_kernel(const float* __restrict__ Wq,
                                                        const float* __restrict__ Wk,
                                                        const float* __restrict__ Wv,
                                                        const float* __restrict__ Wo) {
    int i = blockIdx.x * 256 + threadIdx.x;
    int w = i >> 20;
    int e = i & (WSZ - 1);
    const float* W = (w == 0) ? Wq : (w == 1) ? Wk : (w == 2) ? Wv : Wo;
    __nv_bfloat16 hi, lo;
    bsplit(W[e], hi, lo);
    g_whi[i] = hi; g_wlo[i] = lo;
}

// ========== RoPE table (accurate double trig; immune to fast-math) ==========
__global__ __launch_bounds__(256) void rope_table_kernel() {
    int idx = blockIdx.x * 256 + threadIdx.x;
    if (idx >= S_LEN * 32) return;
    int d = idx & 31;
    int s = idx >> 5;
    double f64   = pow(10000.0, -(double)d / 32.0);
    float  inv32 = (float)f64;
    float  ang32 = (float)s * inv32;
    double c, sn;
    sincos((double)ang32, &sn, &c);
    g_rope[idx] = make_float2((float)c, (float)sn);
}

// ================= Tensor-core flash attention (pipelined) ==================
#define ATSTR 72
#define ASTG  (64 * ATSTR)
#define ATTN_SMEM (2 * 4 * ASTG * 2)     // 73728 B

__global__ __launch_bounds__(256) void attn_tc_kernel() {
    extern __shared__ __nv_bfloat16 adsm[];
    const int tid = threadIdx.x, lane = tid & 31, wid = tid >> 5;
    const int b = blockIdx.z, h = blockIdx.y, q0 = blockIdx.x * 128;
    const int bh = b * NHEAD + h;

    const __nv_bfloat16* Qh = g_qhi + (size_t)bh * S_LEN * HDIM;
    const __nv_bfloat16* Ql = g_qlo + (size_t)bh * S_LEN * HDIM;
    const __nv_bfloat16* Kh = g_khi + (size_t)bh * S_LEN * HDIM;
    const __nv_bfloat16* Kl = g_klo + (size_t)bh * S_LEN * HDIM;
    const __nv_bfloat16* Vh = g_vthi + (size_t)bh * HDIM * S_LEN;
    const __nv_bfloat16* Vl = g_vtlo + (size_t)bh * HDIM * S_LEN;

    // ---- stage Q in smem and extract fragments ----
    uint32_t qh[4][4], ql[4][4];
    {
        const uint32_t sb = smem_u32(adsm);
#pragma unroll
        for (int pass = 0; pass < 2; pass++) {
            const __nv_bfloat16* Qsrc = pass ? Ql : Qh;
#pragma unroll
            for (int i = 0; i < 2; i++) {
                int idx = tid + i * 256;
                int row = idx >> 2;
                int c16 = (idx & 3) * 16;
                *(uint4*)&adsm[row * ATSTR + c16]     = *(const uint4*)(Qsrc + (size_t)(q0 + row) * HDIM + c16);
                *(uint4*)&adsm[row * ATSTR + c16 + 8] = *(const uint4*)(Qsrc + (size_t)(q0 + row) * HDIM + c16 + 8);
            }
            __syncthreads();
#pragma unroll
            for (int ka = 0; ka < 4; ka++) {
                uint32_t a = ldsm_addr_s(sb, wid * 16, ka * 16, lane, ATSTR);
                if (pass == 0) ldsm_x4(qh[ka][0], qh[ka][1], qh[ka][2], qh[ka][3], a);
                else           ldsm_x4(ql[ka][0], ql[ka][1], ql[ka][2], ql[ka][3], a);
            }
            __syncthreads();
        }
    }

    float out[8][4];
#pragma unroll
    for (int na = 0; na < 8; na++)
#pragma unroll
        for (int r = 0; r < 4; r++) out[na][r] = 0.f;
    float m0 = -INFINITY, m1 = -INFINITY, l0 = 0.f, l1 = 0.f;

    auto stage_load = [&](int st, int t) {
        uint32_t b0 = smem_u32(adsm + st * 4 * ASTG);
#pragma unroll
        for (int i = 0; i < 2; i++) {
            int idx = tid + i * 256;
            int row = idx >> 3;
            int c8  = (idx & 7) * 8;
            uint32_t so = (uint32_t)(row * ATSTR + c8) * 2;
            size_t gk = (size_t)(t * 64 + row) * HDIM + c8;
            size_t gv = (size_t)row * S_LEN + t * 64 + c8;
            cp16(b0 + so,            Kh + gk);
            cp16(b0 + ASTG * 2 + so, Kl + gk);
            cp16(b0 + ASTG * 4 + so, Vh + gv);
            cp16(b0 + ASTG * 6 + so, Vl + gv);
        }
    };

    stage_load(0, 0);
    CP_COMMIT();

    for (int t = 0; t < S_LEN / 64; t++) {
        if (t < S_LEN / 64 - 1) stage_load((t + 1) & 1, t + 1);
        CP_COMMIT();
        CP_WAIT1();
        __syncthreads();

        uint32_t b0   = smem_u32(adsm + (t & 1) * 4 * ASTG);
        uint32_t sbKh = b0, sbKl = b0 + ASTG * 2, sbVh = b0 + ASTG * 4, sbVl = b0 + ASTG * 6;

        float sc[8][4];
#pragma unroll
        for (int na = 0; na < 8; na++)
#pragma unroll
            for (int r = 0; r < 4; r++) sc[na][r] = 0.f;

#pragma unroll
        for (int ka = 0; ka < 4; ka++) {
            uint32_t bkh[8][2], bkl[8][2];
#pragma unroll
            for (int p = 0; p < 4; p++) {
                uint32_t r0, r1, r2, r3;
                ldsm_x4(r0, r1, r2, r3, ldsm_addr_s(sbKh, p * 16, ka * 16, lane, ATSTR));
                bkh[p * 2 + 0][0] = r0; bkh[p * 2 + 0][1] = r2;
                bkh[p * 2 + 1][0] = r1; bkh[p * 2 + 1][1] = r3;
                ldsm_x4(r0, r1, r2, r3, ldsm_addr_s(sbKl, p * 16, ka * 16, lane, ATSTR));
                bkl[p * 2 + 0][0] = r0; bkl[p * 2 + 0][1] = r2;
                bkl[p * 2 + 1][0] = r1; bkl[p * 2 + 1][1] = r3;
            }
#pragma unroll
            for (int na = 0; na < 8; na++) {
                mma16816(sc[na], qh[ka], bkh[na]);
                mma16816(sc[na], qh[ka], bkl[na]);
                mma16816(sc[na], ql[ka], bkh[na]);
            }
        }

        float mt0 = -INFINITY, mt1 = -INFINITY;
#pragma unroll
        for (int na = 0; na < 8; na++) {
#pragma unroll
            for (int r = 0; r < 4; r++) sc[na][r] *= 0.125f;
            mt0 = fmaxf(mt0, fmaxf(sc[na][0], sc[na][1]));
            mt1 = fmaxf(mt1, fmaxf(sc[na][2], sc[na][3]));
        }
        mt0 = fmaxf(mt0, __shfl_xor_sync(0xffffffffu, mt0, 1));
        mt0 = fmaxf(mt0, __shfl_xor_sync(0xffffffffu, mt0, 2));
        mt1 = fmaxf(mt1, __shfl_xor_sync(0xffffffffu, mt1, 1));
        mt1 = fmaxf(mt1, __shfl_xor_sync(0xffffffffu, mt1, 2));

        float mn0 = fmaxf(m0, mt0), mn1 = fmaxf(m1, mt1);
        float al0 = __expf(m0 - mn0), al1 = __expf(m1 - mn1);
        m0 = mn0; m1 = mn1;

        uint32_t pA[8], pB[8], pAl[8], pBl[8];
        float rs0 = 0.f, rs1 = 0.f;
#pragma unroll
        for (int na = 0; na < 8; na++) {
            float p00 = __expf(sc[na][0] - m0);
            float p01 = __expf(sc[na][1] - m0);
            float p10 = __expf(sc[na][2] - m1);
            float p11 = __expf(sc[na][3] - m1);
            rs0 += p00 + p01; rs1 += p10 + p11;
            __nv_bfloat162 hv, lv;
            hv.x = __float2bfloat16(p00); hv.y = __float2bfloat16(p01);
            lv.x = __float2bfloat16(p00 - __bfloat162float(hv.x));
            lv.y = __float2bfloat16(p01 - __bfloat162float(hv.y));
            pA[na] = *(uint32_t*)&hv; pAl[na] = *(uint32_t*)&lv;
            hv.x = __float2bfloat16(p10); hv.y = __float2bfloat16(p11);
            lv.x = __float2bfloat16(p10 - __bfloat162float(hv.x));
            lv.y = __float2bfloat16(p11 - __bfloat162float(hv.y));
            pB[na] = *(uint32_t*)&hv; pBl[na] = *(uint32_t*)&lv;
        }
        rs0 += __shfl_xor_sync(0xffffffffu, rs0, 1);
        rs0 += __shfl_xor_sync(0xffffffffu, rs0, 2);
        rs1 += __shfl_xor_sync(0xffffffffu, rs1, 1);
        rs1 += __shfl_xor_sync(0xffffffffu, rs1, 2);
        l0 = l0 * al0 + rs0;
        l1 = l1 * al1 + rs1;
#pragma unroll
        for (int na = 0; na < 8; na++) {
            out[na][0] *= al0; out[na][1] *= al0;
            out[na][2] *= al1; out[na][3] *= al1;
        }

#pragma unroll
        for (int ka = 0; ka < 4; ka++) {
            uint32_t ah[4]  = {pA[2 * ka],  pB[2 * ka],  pA[2 * ka + 1],  pB[2 * ka + 1]};
            uint32_t alo[4] = {pAl[2 * ka], pBl[2 * ka], pAl[2 * ka + 1], pBl[2 * ka + 1]};
            uint32_t bvh[8][2], bvl[8][2];
#pragma unroll
            for (int p = 0; p < 4; p++) {
                uint32_t r0, r1, r2, r3;
                ldsm_x4(r0, r1, r2, r3, ldsm_addr_s(sbVh, p * 16, ka * 16, lane, ATSTR));
                bvh[p * 2 + 0][0] = r0; bvh[p * 2 + 0][1] = r2;
                bvh[p * 2 + 1][0] = r1; bvh[p * 2 + 1][1] = r3;
                ldsm_x4(r0, r1, r2, r3, ldsm_addr_s(sbVl, p * 16, ka * 16, lane, ATSTR));
                bvl[p * 2 + 0][0] = r0; bvl[p * 2 + 0][1] = r2;
                bvl[p * 2 + 1][0] = r1; bvl[p * 2 + 1][1] = r3;
            }
#pragma unroll
            for (int na = 0; na < 8; na++) {
                mma16816(out[na], ah,  bvh[na]);
                mma16816(out[na], ah,  bvl[na]);
                mma16816(out[na], alo, bvh[na]);
            }
        }
        __syncthreads();
    }

    float inv0 = 1.f / l0, inv1 = 1.f / l1;
    int gr  = lane >> 2;
    int gc2 = (lane & 3) * 2;
    int row0 = b * S_LEN + q0 + wid * 16 + gr;
#pragma unroll
    for (int na = 0; na < 8; na++) {
        int col = h * HDIM + na * 8 + gc2;
        float v0 = out[na][0] * inv0, v1 = out[na][1] * inv0;
        float v2 = out[na][2] * inv1, v3 = out[na][3] * inv1;
        __nv_bfloat162 hv, lv;
        hv.x = __float2bfloat16(v0); hv.y = __float2bfloat16(v1);
        lv.x = __float2bfloat16(v0 - __bfloat162float(hv.x));
        lv.y = __float2bfloat16(v1 - __bfloat162float(hv.y));
        *(__nv_bfloat162*)&g_ahi[(size_t)row0 * D_MODEL + col] = hv;
        *(__nv_bfloat162*)&g_alo[(size_t)row0 * D_MODEL + col] = lv;
        hv.x = __float2bfloat16(v2); hv.y = __float2bfloat16(v3);
        lv.x = __float2bfloat16(v2 - __bfloat162float(hv.x));
        lv.y = __float2bfloat16(v3 - __bfloat162float(hv.y));
        *(__nv_bfloat162*)&g_ahi[(size_t)(row0 + 8) * D_MODEL + col] = hv;
        *(__nv_bfloat162*)&g_alo[(size_t)(row0 + 8) * D_MODEL + col] = lv;
    }
}

// ================= launch =================
extern "C" void kernel_launch(void* const* d_in, const int* in_sizes, int n_in,
                              void* d_out, int out_size) {
    int xi = -1;
    for (int i = 0; i < n_in; i++)
        if (in_sizes[i] == M_ROWS * D_MODEL) { xi = i; break; }
    if (xi < 0) xi = 0;
    const float* w[4] = {0, 0, 0, 0};
    int wn = 0;
    for (int i = 0; i < n_in && wn < 4; i++)
        if (i != xi && in_sizes[i] == WSZ)
            w[wn++] = (const float*)d_in[i];

    const float* x  = (const float*)d_in[xi];
    float* out = (float*)d_out;

    cudaFuncSetAttribute(tgemm_qkv_kernel, cudaFuncAttributeMaxDynamicSharedMemorySize, GEMM_SMEM);
    cudaFuncSetAttribute(tgemm_o_kernel,   cudaFuncAttributeMaxDynamicSharedMemorySize, GEMM_SMEM);
    cudaFuncSetAttribute(attn_tc_kernel,   cudaFuncAttributeMaxDynamicSharedMemorySize, ATTN_SMEM);

    rope_table_kernel<<<(S_LEN * 32) / 256, 256>>>();
    convert_x_kernel<<<(M_ROWS * D_MODEL) / 256, 256>>>(x);
    convert_w_kernel<<<(4 * WSZ) / 256, 256>>>(w[0], w[1], w[2], w[3]);

    dim3 gqkv(D_MODEL / 128, M_ROWS / 128, 3);
    tgemm_qkv_kernel<<<gqkv, 256, GEMM_SMEM>>>();

    dim3 gattn(S_LEN / 128, NHEAD, B_SZ);
    attn_tc_kernel<<<gattn, 256, ATTN_SMEM>>>();

    dim3 go(D_MODEL / 128, M_ROWS / 128, 1);
    tgemm_o_kernel<<<go, 256, GEMM_SMEM>>>(out);
}

// round 14
// speedup vs baseline: 1.0242x; 1.0242x over previous
#include <cuda_runtime.h>
#include <cuda_bf16.h>
#include <math.h>
#include <stdint.h>

#define B_SZ    2
#define S_LEN   2048
#define D_MODEL 1024
#define NHEAD   16
#define HDIM    64
#define M_ROWS  (B_SZ * S_LEN)   // 4096
#define WSZ     (D_MODEL * D_MODEL)   // 1M
#define HS      (B_SZ * NHEAD)   // 32 heads total

// ---------------- scratch (device-side only) ----------------
__device__ float  g_q[M_ROWS * D_MODEL];
__device__ float  g_k[M_ROWS * D_MODEL];
__device__ float  g_v[M_ROWS * D_MODEL];
__device__ float2 g_rope[S_LEN * 32];
__device__ __nv_bfloat16 g_xhi[M_ROWS * D_MODEL];
__device__ __nv_bfloat16 g_xlo[M_ROWS * D_MODEL];
__device__ __nv_bfloat16 g_whi[4 * WSZ];
__device__ __nv_bfloat16 g_wlo[4 * WSZ];
__device__ __nv_bfloat16 g_ahi[M_ROWS * D_MODEL];
__device__ __nv_bfloat16 g_alo[M_ROWS * D_MODEL];
__device__ __nv_bfloat16 g_qhi[HS * S_LEN * HDIM];
__device__ __nv_bfloat16 g_qlo[HS * S_LEN * HDIM];
__device__ __nv_bfloat16 g_khi[HS * S_LEN * HDIM];
__device__ __nv_bfloat16 g_klo[HS * S_LEN * HDIM];
__device__ __nv_bfloat16 g_vthi[HS * HDIM * S_LEN];
__device__ __nv_bfloat16 g_vtlo[HS * HDIM * S_LEN];

// ================= helpers =================
__device__ __forceinline__ uint32_t smem_u32(const void* p) {
    uint32_t a;
    asm("{ .reg .u64 t; cvta.to.shared.u64 t, %1; cvt.u32.u64 %0, t; }" : "=r"(a) : "l"(p));
    return a;
}
__device__ __forceinline__ void ldsm_x4(uint32_t& r0, uint32_t& r1, uint32_t& r2, uint32_t& r3,
                                        uint32_t addr) {
    asm volatile("ldmatrix.sync.aligned.m8n8.x4.shared.b16 {%0,%1,%2,%3}, [%4];"
                 : "=r"(r0), "=r"(r1), "=r"(r2), "=r"(r3) : "r"(addr));
}
__device__ __forceinline__ void mma16816(float* c, const uint32_t* a, const uint32_t* b) {
    asm volatile(
        "mma.sync.aligned.m16n8k16.row.col.f32.bf16.bf16.f32 "
        "{%0,%1,%2,%3}, {%4,%5,%6,%7}, {%8,%9}, {%0,%1,%2,%3};"
        : "+f"(c[0]), "+f"(c[1]), "+f"(c[2]), "+f"(c[3])
        : "r"(a[0]), "r"(a[1]), "r"(a[2]), "r"(a[3]), "r"(b[0]), "r"(b[1]));
}
__device__ __forceinline__ void cp16(uint32_t dst, const void* src) {
    asm volatile("cp.async.cg.shared.global [%0], [%1], 16;" :: "r"(dst), "l"(src));
}
#define CP_COMMIT() asm volatile("cp.async.commit_group;" ::: "memory")
#define CP_WAIT1()  asm volatile("cp.async.wait_group 1;" ::: "memory")

__device__ __forceinline__ uint32_t ldsm_addr_s(uint32_t base, int row0, int col0,
                                                int lane, int stride) {
    int sub = lane >> 3, r8 = lane & 7;
    int row = row0 + r8 + (sub & 1) * 8;
    int col = col0 + (sub >> 1) * 8;
    return base + (uint32_t)(row * stride + col) * 2;
}

// ============== pipelined tensor GEMM ======================================
#define TSTR 40
#define STG  (128 * TSTR)                 // elems per buffer
#define GEMM_SMEM (2 * 4 * STG * 2)       // 81920 B

__device__ __forceinline__ void gemm_stage_load(__nv_bfloat16* st,
                                                const __nv_bfloat16* Ahi,
                                                const __nv_bfloat16* Alo,
                                                const __nv_bfloat16* Bhi,
                                                const __nv_bfloat16* Blo,
                                                int m0, int n0, int kb, int tid) {
    uint32_t b0 = smem_u32(st);
#pragma unroll
    for (int i = 0; i < 2; i++) {
        int li  = tid + i * 256;
        int row = li >> 2;
        int c8  = (li & 3) * 8;
        uint32_t so = (uint32_t)(row * TSTR + c8) * 2;
        size_t ga = (size_t)(m0 + row) * D_MODEL + kb + c8;
        size_t gb = (size_t)(n0 + row) * D_MODEL + kb + c8;
        cp16(b0 + so,           Ahi + ga);
        cp16(b0 + STG * 2 + so, Alo + ga);
        cp16(b0 + STG * 4 + so, Bhi + gb);
        cp16(b0 + STG * 6 + so, Blo + gb);
    }
}

__device__ __forceinline__ void tgemm_tile(const __nv_bfloat16* __restrict__ Ahi,
                                           const __nv_bfloat16* __restrict__ Alo,
                                           const __nv_bfloat16* __restrict__ Bhi,
                                           const __nv_bfloat16* __restrict__ Blo,
                                           float* __restrict__ C, int m0, int n0) {
    extern __shared__ __nv_bfloat16 dsm[];
    const int tid  = threadIdx.x;
    const int lane = tid & 31;
    const int wid  = tid >> 5;
    const int wm   = (wid & 1) * 64;
    const int wn   = (wid >> 1) * 32;

    float acc[4][4][4];
#pragma unroll
    for (int i = 0; i < 4; i++)
#pragma unroll
        for (int j = 0; j < 4; j++)
#pragma unroll
            for (int r = 0; r < 4; r++) acc[i][j][r] = 0.f;

    gemm_stage_load(dsm, Ahi, Alo, Bhi, Blo, m0, n0, 0, tid);
    CP_COMMIT();

    for (int ch = 0; ch < 32; ch++) {
        if (ch < 31)
            gemm_stage_load(dsm + ((ch + 1) & 1) * 4 * STG, Ahi, Alo, Bhi, Blo,
                            m0, n0, (ch + 1) * 32, tid);
        CP_COMMIT();
        CP_WAIT1();
        __syncthreads();

        uint32_t b0  = smem_u32(dsm + (ch & 1) * 4 * STG);
        uint32_t bAh = b0, bAl = b0 + STG * 2, bBh = b0 + STG * 4, bBl = b0 + STG * 6;

#pragma unroll
        for (int ks = 0; ks < 2; ks++) {
            const int kk = ks * 16;
            uint32_t afh[4][4], afl[4][4];
#pragma unroll
            for (int ma = 0; ma < 4; ma++) {
                ldsm_x4(afh[ma][0], afh[ma][1], afh[ma][2], afh[ma][3],
                        ldsm_addr_s(bAh, wm + ma * 16, kk, lane, TSTR));
                ldsm_x4(afl[ma][0], afl[ma][1], afl[ma][2], afl[ma][3],
                        ldsm_addr_s(bAl, wm + ma * 16, kk, lane, TSTR));
            }
            uint32_t bfh[4][2], bfl[4][2];
#pragma unroll
            for (int p = 0; p < 2; p++) {
                uint32_t r0, r1, r2, r3;
                ldsm_x4(r0, r1, r2, r3, ldsm_addr_s(bBh, wn + p * 16, kk, lane, TSTR));
                bfh[p * 2 + 0][0] = r0; bfh[p * 2 + 0][1] = r2;
                bfh[p * 2 + 1][0] = r1; bfh[p * 2 + 1][1] = r3;
                ldsm_x4(r0, r1, r2, r3, ldsm_addr_s(bBl, wn + p * 16, kk, lane, TSTR));
                bfl[p * 2 + 0][0] = r0; bfl[p * 2 + 0][1] = r2;
                bfl[p * 2 + 1][0] = r1; bfl[p * 2 + 1][1] = r3;
            }
#pragma unroll
            for (int ma = 0; ma < 4; ma++)
#pragma unroll
                for (int na = 0; na < 4; na++) {
                    mma16816(acc[ma][na], afh[ma], bfh[na]);
                    mma16816(acc[ma][na], afh[ma], bfl[na]);
                    mma16816(acc[ma][na], afl[ma], bfh[na]);
                }
        }
        // NOTE: no trailing __syncthreads() — next iteration's cp.async targets
        // the other stage buffer, and iter ch+2 (same buffer) is unreachable
        // without passing iter ch+1's top barrier, which orders all reads of
        // this buffer. (R14 change; revert if regression.)
    }

#pragma unroll
    for (int ma = 0; ma < 4; ma++)
#pragma unroll
        for (int na = 0; na < 4; na++) {
            int r = m0 + wm + ma * 16 + (lane >> 2);
            int c = n0 + wn + na * 8 + (lane & 3) * 2;
            *(float2*)(C + (size_t)r * D_MODEL + c)       = make_float2(acc[ma][na][0], acc[ma][na][1]);
            *(float2*)(C + (size_t)(r + 8) * D_MODEL + c) = make_float2(acc[ma][na][2], acc[ma][na][3]);
        }
}

__global__ __launch_bounds__(256) void tgemm_qkv_kernel() {
    int z = blockIdx.z;
    float* C = (z == 0) ? g_q : (z == 1) ? g_k : g_v;
    tgemm_tile(g_xhi, g_xlo, g_whi + (size_t)z * WSZ, g_wlo + (size_t)z * WSZ,
               C, blockIdx.y * 128, blockIdx.x * 128);
}
__global__ __launch_bounds__(256) void tgemm_o_kernel(float* __restrict__ C) {
    tgemm_tile(g_ahi, g_alo, g_whi + (size_t)3 * WSZ, g_wlo + (size_t)3 * WSZ,
               C, blockIdx.y * 128, blockIdx.x * 128);
}

// ================= bf16-split conversions =================
__global__ __launch_bounds__(256) void convert_x_kernel(const float* __restrict__ x) {
    int i = blockIdx.x * 256 + threadIdx.x;
    float v = x[i];
    __nv_bfloat16 hi = __float2bfloat16(v);
    g_xhi[i] = hi;
    g_xlo[i] = __float2bfloat16(v - __bfloat162float(hi));
}
__global__ __launch_bounds__(256) void convert_w_kernel(const float* __restrict__ Wq,
                                                        const float* __restrict__ Wk,
                                                        const float* __restrict__ Wv,
                                                        const float* __restrict__ Wo) {
    int i = blockIdx.x * 256 + threadIdx.x;
    int w = i >> 20;
    int e = i & (WSZ - 1);
    const float* W = (w == 0) ? Wq : (w == 1) ? Wk : (w == 2) ? Wv : Wo;
    float v = W[e];
    __nv_bfloat16 hi = __float2bfloat16(v);
    g_whi[i] = hi;
    g_wlo[i] = __float2bfloat16(v - __bfloat162float(hi));
}

// ========== RoPE table (accurate double trig; immune to fast-math) ==========
__global__ __launch_bounds__(256) void rope_table_kernel() {
    int idx = blockIdx.x * 256 + threadIdx.x;
    if (idx >= S_LEN * 32) return;
    int d = idx & 31;
    int s = idx >> 5;
    double f64   = pow(10000.0, -(double)d / 32.0);
    float  inv32 = (float)f64;
    float  ang32 = (float)s * inv32;
    double c, sn;
    sincos((double)ang32, &sn, &c);
    g_rope[idx] = make_float2((float)c, (float)sn);
}

// ===== RoPE + bf16-split + head-major relayout for q,k ======================
__global__ __launch_bounds__(256) void ropeconv_kernel() {
    int idx = blockIdx.x * 256 + threadIdx.x;
    int d    = idx & 31;
    int h    = (idx >> 5) & 15;
    int grow = idx >> 9;
    int s    = grow & (S_LEN - 1);
    int b    = grow >> 11;

    float2 cs = g_rope[s * 32 + d];
    float c = cs.x, sn = cs.y;

    size_t src = (size_t)grow * D_MODEL + h * HDIM + d;
    float q1 = g_q[src], q2 = g_q[src + 32];
    float k1 = g_k[src], k2 = g_k[src + 32];
    float qa = q1 * c - q2 * sn;
    float qb = q2 * c + q1 * sn;
    float ka = k1 * c - k2 * sn;
    float kb = k2 * c + k1 * sn;

    size_t dst = ((size_t)(b * NHEAD + h) * S_LEN + s) * HDIM + d;
    __nv_bfloat16 t;
    t = __float2bfloat16(qa); g_qhi[dst]      = t; g_qlo[dst]      = __float2bfloat16(qa - __bfloat162float(t));
    t = __float2bfloat16(qb); g_qhi[dst + 32] = t; g_qlo[dst + 32] = __float2bfloat16(qb - __bfloat162float(t));
    t = __float2bfloat16(ka); g_khi[dst]      = t; g_klo[dst]      = __float2bfloat16(ka - __bfloat162float(t));
    t = __float2bfloat16(kb); g_khi[dst + 32] = t; g_klo[dst + 32] = __float2bfloat16(kb - __bfloat162float(t));
}

// ===== V transpose + bf16 split =============================================
__global__ __launch_bounds__(256) void vtrans_kernel() {
    __shared__ float tile[64][65];
    int bh = blockIdx.y;
    int s0 = blockIdx.x * 64;
    int b = bh >> 4, h = bh & 15;
    int tid = threadIdx.x;

#pragma unroll
    for (int i = 0; i < 16; i++) {
        int idx = tid + i * 256;
        int s = idx >> 6, d = idx & 63;
        tile[s][d] = g_v[(size_t)(b * S_LEN + s0 + s) * D_MODEL + h * HDIM + d];
    }
    __syncthreads();
#pragma unroll
    for (int i = 0; i < 16; i++) {
        int idx = tid + i * 256;
        int d = idx >> 6, s = idx & 63;
        float v = tile[s][d];
        __nv_bfloat16 hi = __float2bfloat16(v);
        size_t dst = ((size_t)bh * HDIM + d) * S_LEN + s0 + s;
        g_vthi[dst] = hi;
        g_vtlo[dst] = __float2bfloat16(v - __bfloat162float(hi));
    }
}

// ================= Tensor-core flash attention (pipelined) ==================
#define ATSTR 72
#define ASTG  (64 * ATSTR)
#define ATTN_SMEM (2 * 4 * ASTG * 2)     // 73728 B

__global__ __launch_bounds__(256) void attn_tc_kernel() {
    extern __shared__ __nv_bfloat16 adsm[];
    const int tid = threadIdx.x, lane = tid & 31, wid = tid >> 5;
    const int b = blockIdx.z, h = blockIdx.y, q0 = blockIdx.x * 128;
    const int bh = b * NHEAD + h;

    const __nv_bfloat16* Qh = g_qhi + (size_t)bh * S_LEN * HDIM;
    const __nv_bfloat16* Ql = g_qlo + (size_t)bh * S_LEN * HDIM;
    const __nv_bfloat16* Kh = g_khi + (size_t)bh * S_LEN * HDIM;
    const __nv_bfloat16* Kl = g_klo + (size_t)bh * S_LEN * HDIM;
    const __nv_bfloat16* Vh = g_vthi + (size_t)bh * HDIM * S_LEN;
    const __nv_bfloat16* Vl = g_vtlo + (size_t)bh * HDIM * S_LEN;

    // ---- stage Q in smem and extract fragments ----
    uint32_t qh[4][4], ql[4][4];
    {
        const uint32_t sb = smem_u32(adsm);
#pragma unroll
        for (int pass = 0; pass < 2; pass++) {
            const __nv_bfloat16* Qsrc = pass ? Ql : Qh;
#pragma unroll
            for (int i = 0; i < 2; i++) {
                int idx = tid + i * 256;
                int row = idx >> 2;
                int c16 = (idx & 3) * 16;
                *(uint4*)&adsm[row * ATSTR + c16]     = *(const uint4*)(Qsrc + (size_t)(q0 + row) * HDIM + c16);
                *(uint4*)&adsm[row * ATSTR + c16 + 8] = *(const uint4*)(Qsrc + (size_t)(q0 + row) * HDIM + c16 + 8);
            }
            __syncthreads();
#pragma unroll
            for (int ka = 0; ka < 4; ka++) {
                uint32_t a = ldsm_addr_s(sb, wid * 16, ka * 16, lane, ATSTR);
                if (pass == 0) ldsm_x4(qh[ka][0], qh[ka][1], qh[ka][2], qh[ka][3], a);
                else           ldsm_x4(ql[ka][0], ql[ka][1], ql[ka][2], ql[ka][3], a);
            }
            __syncthreads();
        }
    }

    float out[8][4];
#pragma unroll
    for (int na = 0; na < 8; na++)
#pragma unroll
        for (int r = 0; r < 4; r++) out[na][r] = 0.f;
    float m0 = -INFINITY, m1 = -INFINITY, l0 = 0.f, l1 = 0.f;

    auto stage_load = [&](int st, int t) {
        uint32_t b0 = smem_u32(adsm + st * 4 * ASTG);
#pragma unroll
        for (int i = 0; i < 2; i++) {
            int idx = tid + i * 256;
            int row = idx >> 3;
            int c8  = (idx & 7) * 8;
            uint32_t so = (uint32_t)(row * ATSTR + c8) * 2;
            size_t gk = (size_t)(t * 64 + row) * HDIM + c8;
            size_t gv = (size_t)row * S_LEN + t * 64 + c8;
            cp16(b0 + so,            Kh + gk);
            cp16(b0 + ASTG * 2 + so, Kl + gk);
            cp16(b0 + ASTG * 4 + so, Vh + gv);
            cp16(b0 + ASTG * 6 + so, Vl + gv);
        }
    };

    stage_load(0, 0);
    CP_COMMIT();

    for (int t = 0; t < S_LEN / 64; t++) {
        if (t < S_LEN / 64 - 1) stage_load((t + 1) & 1, t + 1);
        CP_COMMIT();
        CP_WAIT1();
        __syncthreads();

        uint32_t b0   = smem_u32(adsm + (t & 1) * 4 * ASTG);
        uint32_t sbKh = b0, sbKl = b0 + ASTG * 2, sbVh = b0 + ASTG * 4, sbVl = b0 + ASTG * 6;

        float sc[8][4];
#pragma unroll
        for (int na = 0; na < 8; na++)
#pragma unroll
            for (int r = 0; r < 4; r++) sc[na][r] = 0.f;

#pragma unroll
        for (int ka = 0; ka < 4; ka++) {
            uint32_t bkh[8][2], bkl[8][2];
#pragma unroll
            for (int p = 0; p < 4; p++) {
                uint32_t r0, r1, r2, r3;
                ldsm_x4(r0, r1, r2, r3, ldsm_addr_s(sbKh, p * 16, ka * 16, lane, ATSTR));
                bkh[p * 2 + 0][0] = r0; bkh[p * 2 + 0][1] = r2;
                bkh[p * 2 + 1][0] = r1; bkh[p * 2 + 1][1] = r3;
                ldsm_x4(r0, r1, r2, r3, ldsm_addr_s(sbKl, p * 16, ka * 16, lane, ATSTR));
                bkl[p * 2 + 0][0] = r0; bkl[p * 2 + 0][1] = r2;
                bkl[p * 2 + 1][0] = r1; bkl[p * 2 + 1][1] = r3;
            }
#pragma unroll
            for (int na = 0; na < 8; na++) {
                mma16816(sc[na], qh[ka], bkh[na]);
                mma16816(sc[na], qh[ka], bkl[na]);
                mma16816(sc[na], ql[ka], bkh[na]);
            }
        }

        float mt0 = -INFINITY, mt1 = -INFINITY;
#pragma unroll
        for (int na = 0; na < 8; na++) {
#pragma unroll
            for (int r = 0; r < 4; r++) sc[na][r] *= 0.125f;
            mt0 = fmaxf(mt0, fmaxf(sc[na][0], sc[na][1]));
            mt1 = fmaxf(mt1, fmaxf(sc[na][2], sc[na][3]));
        }
        mt0 = fmaxf(mt0, __shfl_xor_sync(0xffffffffu, mt0, 1));
        mt0 = fmaxf(mt0, __shfl_xor_sync(0xffffffffu, mt0, 2));
        mt1 = fmaxf(mt1, __shfl_xor_sync(0xffffffffu, mt1, 1));
        mt1 = fmaxf(mt1, __shfl_xor_sync(0xffffffffu, mt1, 2));

        float mn0 = fmaxf(m0, mt0), mn1 = fmaxf(m1, mt1);
        float al0 = __expf(m0 - mn0), al1 = __expf(m1 - mn1);
        m0 = mn0; m1 = mn1;

        uint32_t pA[8], pB[8], pAl[8], pBl[8];
        float rs0 = 0.f, rs1 = 0.f;
#pragma unroll
        for (int na = 0; na < 8; na++) {
            float p00 = __expf(sc[na][0] - m0);
            float p01 = __expf(sc[na][1] - m0);
            float p10 = __expf(sc[na][2] - m1);
            float p11 = __expf(sc[na][3] - m1);
            rs0 += p00 + p01; rs1 += p10 + p11;
            __nv_bfloat162 hv, lv;
            hv.x = __float2bfloat16(p00); hv.y = __float2bfloat16(p01);
            lv.x = __float2bfloat16(p00 - __bfloat162float(hv.x));
            lv.y = __float2bfloat16(p01 - __bfloat162float(hv.y));
            pA[na] = *(uint32_t*)&hv; pAl[na] = *(uint32_t*)&lv;
            hv.x = __float2bfloat16(p10); hv.y = __float2bfloat16(p11);
            lv.x = __float2bfloat16(p10 - __bfloat162float(hv.x));
            lv.y = __float2bfloat16(p11 - __bfloat162float(hv.y));
            pB[na] = *(uint32_t*)&hv; pBl[na] = *(uint32_t*)&lv;
        }
        rs0 += __shfl_xor_sync(0xffffffffu, rs0, 1);
        rs0 += __shfl_xor_sync(0xffffffffu, rs0, 2);
        rs1 += __shfl_xor_sync(0xffffffffu, rs1, 1);
        rs1 += __shfl_xor_sync(0xffffffffu, rs1, 2);
        l0 = l0 * al0 + rs0;
        l1 = l1 * al1 + rs1;
#pragma unroll
        for (int na = 0; na < 8; na++) {
            out[na][0] *= al0; out[na][1] *= al0;
            out[na][2] *= al1; out[na][3] *= al1;
        }

#pragma unroll
        for (int ka = 0; ka < 4; ka++) {
            uint32_t ah[4]  = {pA[2 * ka],  pB[2 * ka],  pA[2 * ka + 1],  pB[2 * ka + 1]};
            uint32_t alo[4] = {pAl[2 * ka], pBl[2 * ka], pAl[2 * ka + 1], pBl[2 * ka + 1]};
            uint32_t bvh[8][2], bvl[8][2];
#pragma unroll
            for (int p = 0; p < 4; p++) {
                uint32_t r0, r1, r2, r3;
                ldsm_x4(r0, r1, r2, r3, ldsm_addr_s(sbVh, p * 16, ka * 16, lane, ATSTR));
                bvh[p * 2 + 0][0] = r0; bvh[p * 2 + 0][1] = r2;
                bvh[p * 2 + 1][0] = r1; bvh[p * 2 + 1][1] = r3;
                ldsm_x4(r0, r1, r2, r3, ldsm_addr_s(sbVl, p * 16, ka * 16, lane, ATSTR));
                bvl[p * 2 + 0][0] = r0; bvl[p * 2 + 0][1] = r2;
                bvl[p * 2 + 1][0] = r1; bvl[p * 2 + 1][1] = r3;
            }
#pragma unroll
            for (int na = 0; na < 8; na++) {
                mma16816(out[na], ah,  bvh[na]);
                mma16816(out[na], ah,  bvl[na]);
                mma16816(out[na], alo, bvh[na]);
            }
        }
        // no trailing __syncthreads() — same double-buffer safety argument.
    }

    float inv0 = 1.f / l0, inv1 = 1.f / l1;
    int gr  = lane >> 2;
    int gc2 = (lane & 3) * 2;
    int row0 = b * S_LEN + q0 + wid * 16 + gr;
#pragma unroll
    for (int na = 0; na < 8; na++) {
        int col = h * HDIM + na * 8 + gc2;
        float v0 = out[na][0] * inv0, v1 = out[na][1] * inv0;
        float v2 = out[na][2] * inv1, v3 = out[na][3] * inv1;
        __nv_bfloat162 hv, lv;
        hv.x = __float2bfloat16(v0); hv.y = __float2bfloat16(v1);
        lv.x = __float2bfloat16(v0 - __bfloat162float(hv.x));
        lv.y = __float2bfloat16(v1 - __bfloat162float(hv.y));
        *(__nv_bfloat162*)&g_ahi[(size_t)row0 * D_MODEL + col] = hv;
        *(__nv_bfloat162*)&g_alo[(size_t)row0 * D_MODEL + col] = lv;
        hv.x = __float2bfloat16(v2); hv.y = __float2bfloat16(v3);
        lv.x = __float2bfloat16(v2 - __bfloat162float(hv.x));
        lv.y = __float2bfloat16(v3 - __bfloat162float(hv.y));
        *(__nv_bfloat162*)&g_ahi[(size_t)(row0 + 8) * D_MODEL + col] = hv;
        *(__nv_bfloat162*)&g_alo[(size_t)(row0 + 8) * D_MODEL + col] = lv;
    }
}

// ================= launch =================
extern "C" void kernel_launch(void* const* d_in, const int* in_sizes, int n_in,
                              void* d_out, int out_size) {
    int xi = -1;
    for (int i = 0; i < n_in; i++)
        if (in_sizes[i] == M_ROWS * D_MODEL) { xi = i; break; }
    if (xi < 0) xi = 0;
    const float* w[4] = {0, 0, 0, 0};
    int wn = 0;
    for (int i = 0; i < n_in && wn < 4; i++)
        if (i != xi && in_sizes[i] == WSZ)
            w[wn++] = (const float*)d_in[i];

    const float* x  = (const float*)d_in[xi];
    float* out = (float*)d_out;

    cudaFuncSetAttribute(tgemm_qkv_kernel, cudaFuncAttributeMaxDynamicSharedMemorySize, GEMM_SMEM);
    cudaFuncSetAttribute(tgemm_o_kernel,   cudaFuncAttributeMaxDynamicSharedMemorySize, GEMM_SMEM);
    cudaFuncSetAttribute(attn_tc_kernel,   cudaFuncAttributeMaxDynamicSharedMemorySize, ATTN_SMEM);

    convert_x_kernel<<<(M_ROWS * D_MODEL) / 256, 256>>>(x);
    convert_w_kernel<<<(4 * WSZ) / 256, 256>>>(w[0], w[1], w[2], w[3]);

    dim3 gqkv(D_MODEL / 128, M_ROWS / 128, 3);
    tgemm_qkv_kernel<<<gqkv, 256, GEMM_SMEM>>>();

    rope_table_kernel<<<(S_LEN * 32) / 256, 256>>>();
    ropeconv_kernel<<<(M_ROWS * NHEAD * 32) / 256, 256>>>();

    dim3 gvt(S_LEN / 64, HS, 1);
    vtrans_kernel<<<gvt, 256>>>();

    dim3 gattn(S_LEN / 128, NHEAD, B_SZ);
    attn_tc_kernel<<<gattn, 256, ATTN_SMEM>>>();

    dim3 go(D_MODEL / 128, M_ROWS / 128, 1);
    tgemm_o_kernel<<<go, 256, GEMM_SMEM>>>(out);
}

// round 16
// speedup vs baseline: 1.5084x; 1.4727x over previous
#include <cuda_runtime.h>
#include <cuda_bf16.h>
#include <math.h>
#include <stdint.h>

#define B_SZ    2
#define S_LEN   2048
#define D_MODEL 1024
#define NHEAD   16
#define HDIM    64
#define M_ROWS  (B_SZ * S_LEN)   // 4096
#define WSZ     (D_MODEL * D_MODEL)   // 1M
#define HS      (B_SZ * NHEAD)   // 32 heads total

// ---------------- scratch (device-side only) ----------------
__device__ float  g_q[M_ROWS * D_MODEL];
__device__ float  g_k[M_ROWS * D_MODEL];
__device__ float  g_v[M_ROWS * D_MODEL];
__device__ float2 g_rope[S_LEN * 32];
__device__ __nv_bfloat16 g_xhi[M_ROWS * D_MODEL];
__device__ __nv_bfloat16 g_xlo[M_ROWS * D_MODEL];
__device__ __nv_bfloat16 g_whi[4 * WSZ];
__device__ __nv_bfloat16 g_wlo[4 * WSZ];
__device__ __nv_bfloat16 g_ahi[M_ROWS * D_MODEL];
__device__ __nv_bfloat16 g_alo[M_ROWS * D_MODEL];
__device__ __nv_bfloat16 g_qhi[HS * S_LEN * HDIM];
__device__ __nv_bfloat16 g_qlo[HS * S_LEN * HDIM];
__device__ __nv_bfloat16 g_khi[HS * S_LEN * HDIM];
__device__ __nv_bfloat16 g_klo[HS * S_LEN * HDIM];
__device__ __nv_bfloat16 g_vthi[HS * HDIM * S_LEN];
__device__ __nv_bfloat16 g_vtlo[HS * HDIM * S_LEN];

// ================= helpers =================
__device__ __forceinline__ uint32_t smem_u32(const void* p) {
    uint32_t a;
    asm("{ .reg .u64 t; cvta.to.shared.u64 t, %1; cvt.u32.u64 %0, t; }" : "=r"(a) : "l"(p));
    return a;
}
__device__ __forceinline__ void ldsm_x4(uint32_t& r0, uint32_t& r1, uint32_t& r2, uint32_t& r3,
                                        uint32_t addr) {
    asm volatile("ldmatrix.sync.aligned.m8n8.x4.shared.b16 {%0,%1,%2,%3}, [%4];"
                 : "=r"(r0), "=r"(r1), "=r"(r2), "=r"(r3) : "r"(addr));
}
__device__ __forceinline__ void mma16816(float* c, const uint32_t* a, const uint32_t* b) {
    asm volatile(
        "mma.sync.aligned.m16n8k16.row.col.f32.bf16.bf16.f32 "
        "{%0,%1,%2,%3}, {%4,%5,%6,%7}, {%8,%9}, {%0,%1,%2,%3};"
        : "+f"(c[0]), "+f"(c[1]), "+f"(c[2]), "+f"(c[3])
        : "r"(a[0]), "r"(a[1]), "r"(a[2]), "r"(a[3]), "r"(b[0]), "r"(b[1]));
}
__device__ __forceinline__ void cp16(uint32_t dst, const void* src) {
    asm volatile("cp.async.cg.shared.global [%0], [%1], 16;" :: "r"(dst), "l"(src));
}
#define CP_COMMIT() asm volatile("cp.async.commit_group;" ::: "memory")
#define CP_WAIT1()  asm volatile("cp.async.wait_group 1;" ::: "memory")

__device__ __forceinline__ uint32_t ldsm_addr_s(uint32_t base, int row0, int col0,
                                                int lane, int stride) {
    int sub = lane >> 3, r8 = lane & 7;
    int row = row0 + r8 + (sub & 1) * 8;
    int col = col0 + (sub >> 1) * 8;
    return base + (uint32_t)(row * stride + col) * 2;
}

// ============== pipelined tensor GEMM ======================================
#define TSTR 40
#define STG  (128 * TSTR)                 // elems per buffer
#define GEMM_SMEM (2 * 4 * STG * 2)       // 81920 B

__device__ __forceinline__ void gemm_stage_load(__nv_bfloat16* st,
                                                const __nv_bfloat16* Ahi,
                                                const __nv_bfloat16* Alo,
                                                const __nv_bfloat16* Bhi,
                                                const __nv_bfloat16* Blo,
                                                int m0, int n0, int kb, int tid) {
    uint32_t b0 = smem_u32(st);
#pragma unroll
    for (int i = 0; i < 2; i++) {
        int li  = tid + i * 256;
        int row = li >> 2;
        int c8  = (li & 3) * 8;
        uint32_t so = (uint32_t)(row * TSTR + c8) * 2;
        size_t ga = (size_t)(m0 + row) * D_MODEL + kb + c8;
        size_t gb = (size_t)(n0 + row) * D_MODEL + kb + c8;
        cp16(b0 + so,           Ahi + ga);
        cp16(b0 + STG * 2 + so, Alo + ga);
        cp16(b0 + STG * 4 + so, Bhi + gb);
        cp16(b0 + STG * 6 + so, Blo + gb);
    }
}

__device__ __forceinline__ void tgemm_tile(const __nv_bfloat16* __restrict__ Ahi,
                                           const __nv_bfloat16* __restrict__ Alo,
                                           const __nv_bfloat16* __restrict__ Bhi,
                                           const __nv_bfloat16* __restrict__ Blo,
                                           float* __restrict__ C, int m0, int n0) {
    extern __shared__ __nv_bfloat16 dsm[];
    const int tid  = threadIdx.x;
    const int lane = tid & 31;
    const int wid  = tid >> 5;
    const int wm   = (wid & 1) * 64;
    const int wn   = (wid >> 1) * 32;

    float acc[4][4][4];
#pragma unroll
    for (int i = 0; i < 4; i++)
#pragma unroll
        for (int j = 0; j < 4; j++)
#pragma unroll
            for (int r = 0; r < 4; r++) acc[i][j][r] = 0.f;

    gemm_stage_load(dsm, Ahi, Alo, Bhi, Blo, m0, n0, 0, tid);
    CP_COMMIT();

    for (int ch = 0; ch < 32; ch++) {
        if (ch < 31)
            gemm_stage_load(dsm + ((ch + 1) & 1) * 4 * STG, Ahi, Alo, Bhi, Blo,
                            m0, n0, (ch + 1) * 32, tid);
        CP_COMMIT();
        CP_WAIT1();
        __syncthreads();

        uint32_t b0  = smem_u32(dsm + (ch & 1) * 4 * STG);
        uint32_t bAh = b0, bAl = b0 + STG * 2, bBh = b0 + STG * 4, bBl = b0 + STG * 6;

#pragma unroll
        for (int ks = 0; ks < 2; ks++) {
            const int kk = ks * 16;
            uint32_t afh[4][4], afl[4][4];
#pragma unroll
            for (int ma = 0; ma < 4; ma++) {
                ldsm_x4(afh[ma][0], afh[ma][1], afh[ma][2], afh[ma][3],
                        ldsm_addr_s(bAh, wm + ma * 16, kk, lane, TSTR));
                ldsm_x4(afl[ma][0], afl[ma][1], afl[ma][2], afl[ma][3],
                        ldsm_addr_s(bAl, wm + ma * 16, kk, lane, TSTR));
            }
            uint32_t bfh[4][2], bfl[4][2];
#pragma unroll
            for (int p = 0; p < 2; p++) {
                uint32_t r0, r1, r2, r3;
                ldsm_x4(r0, r1, r2, r3, ldsm_addr_s(bBh, wn + p * 16, kk, lane, TSTR));
                bfh[p * 2 + 0][0] = r0; bfh[p * 2 + 0][1] = r2;
                bfh[p * 2 + 1][0] = r1; bfh[p * 2 + 1][1] = r3;
                ldsm_x4(r0, r1, r2, r3, ldsm_addr_s(bBl, wn + p * 16, kk, lane, TSTR));
                bfl[p * 2 + 0][0] = r0; bfl[p * 2 + 0][1] = r2;
                bfl[p * 2 + 1][0] = r1; bfl[p * 2 + 1][1] = r3;
            }
#pragma unroll
            for (int ma = 0; ma < 4; ma++)
#pragma unroll
                for (int na = 0; na < 4; na++) {
                    mma16816(acc[ma][na], afh[ma], bfh[na]);
                    mma16816(acc[ma][na], afh[ma], bfl[na]);
                    mma16816(acc[ma][na], afl[ma], bfh[na]);
                }
        }
        __syncthreads();
    }

#pragma unroll
    for (int ma = 0; ma < 4; ma++)
#pragma unroll
        for (int na = 0; na < 4; na++) {
            int r = m0 + wm + ma * 16 + (lane >> 2);
            int c = n0 + wn + na * 8 + (lane & 3) * 2;
            *(float2*)(C + (size_t)r * D_MODEL + c)       = make_float2(acc[ma][na][0], acc[ma][na][1]);
            *(float2*)(C + (size_t)(r + 8) * D_MODEL + c) = make_float2(acc[ma][na][2], acc[ma][na][3]);
        }
}

__global__ __launch_bounds__(256) void tgemm_qkv_kernel() {
    int z = blockIdx.z;
    float* C = (z == 0) ? g_q : (z == 1) ? g_k : g_v;
    tgemm_tile(g_xhi, g_xlo, g_whi + (size_t)z * WSZ, g_wlo + (size_t)z * WSZ,
               C, blockIdx.y * 128, blockIdx.x * 128);
}
__global__ __launch_bounds__(256) void tgemm_o_kernel(float* __restrict__ C) {
    tgemm_tile(g_ahi, g_alo, g_whi + (size_t)3 * WSZ, g_wlo + (size_t)3 * WSZ,
               C, blockIdx.y * 128, blockIdx.x * 128);
}

// ================= bf16-split conversions =================
__global__ __launch_bounds__(256) void convert_x_kernel(const float* __restrict__ x) {
    int i = blockIdx.x * 256 + threadIdx.x;
    float v = x[i];
    __nv_bfloat16 hi = __float2bfloat16(v);
    g_xhi[i] = hi;
    g_xlo[i] = __float2bfloat16(v - __bfloat162float(hi));
}
__global__ __launch_bounds__(256) void convert_w_kernel(const float* __restrict__ Wq,
                                                        const float* __restrict__ Wk,
                                                        const float* __restrict__ Wv,
                                                        const float* __restrict__ Wo) {
    int i = blockIdx.x * 256 + threadIdx.x;
    int w = i >> 20;
    int e = i & (WSZ - 1);
    const float* W = (w == 0) ? Wq : (w == 1) ? Wk : (w == 2) ? Wv : Wo;
    float v = W[e];
    __nv_bfloat16 hi = __float2bfloat16(v);
    g_whi[i] = hi;
    g_wlo[i] = __float2bfloat16(v - __bfloat162float(hi));
}

// ========== RoPE table (accurate double trig; immune to fast-math) ==========
__global__ __launch_bounds__(256) void rope_table_kernel() {
    int idx = blockIdx.x * 256 + threadIdx.x;
    if (idx >= S_LEN * 32) return;
    int d = idx & 31;
    int s = idx >> 5;
    double f64   = pow(10000.0, -(double)d / 32.0);
    float  inv32 = (float)f64;
    float  ang32 = (float)s * inv32;
    double c, sn;
    sincos((double)ang32, &sn, &c);
    g_rope[idx] = make_float2((float)c, (float)sn);
}

// ===== RoPE + bf16-split + head-major relayout for q,k ======================
__global__ __launch_bounds__(256) void ropeconv_kernel() {
    int idx = blockIdx.x * 256 + threadIdx.x;
    int d    = idx & 31;
    int h    = (idx >> 5) & 15;
    int grow = idx >> 9;
    int s    = grow & (S_LEN - 1);
    int b    = grow >> 11;

    float2 cs = g_rope[s * 32 + d];
    float c = cs.x, sn = cs.y;

    size_t src = (size_t)grow * D_MODEL + h * HDIM + d;
    float q1 = g_q[src], q2 = g_q[src + 32];
    float k1 = g_k[src], k2 = g_k[src + 32];
    float qa = q1 * c - q2 * sn;
    float qb = q2 * c + q1 * sn;
    float ka = k1 * c - k2 * sn;
    float kb = k2 * c + k1 * sn;

    size_t dst = ((size_t)(b * NHEAD + h) * S_LEN + s) * HDIM + d;
    __nv_bfloat16 t;
    t = __float2bfloat16(qa); g_qhi[dst]      = t; g_qlo[dst]      = __float2bfloat16(qa - __bfloat162float(t));
    t = __float2bfloat16(qb); g_qhi[dst + 32] = t; g_qlo[dst + 32] = __float2bfloat16(qb - __bfloat162float(t));
    t = __float2bfloat16(ka); g_khi[dst]      = t; g_klo[dst]      = __float2bfloat16(ka - __bfloat162float(t));
    t = __float2bfloat16(kb); g_khi[dst + 32] = t; g_klo[dst + 32] = __float2bfloat16(kb - __bfloat162float(t));
}

// ===== V transpose + bf16 split =============================================
__global__ __launch_bounds__(256) void vtrans_kernel() {
    __shared__ float tile[64][65];
    int bh = blockIdx.y;
    int s0 = blockIdx.x * 64;
    int b = bh >> 4, h = bh & 15;
    int tid = threadIdx.x;

#pragma unroll
    for (int i = 0; i < 16; i++) {
        int idx = tid + i * 256;
        int s = idx >> 6, d = idx & 63;
        tile[s][d] = g_v[(size_t)(b * S_LEN + s0 + s) * D_MODEL + h * HDIM + d];
    }
    __syncthreads();
#pragma unroll
    for (int i = 0; i < 16; i++) {
        int idx = tid + i * 256;
        int d = idx >> 6, s = idx & 63;
        float v = tile[s][d];
        __nv_bfloat16 hi = __float2bfloat16(v);
        size_t dst = ((size_t)bh * HDIM + d) * S_LEN + s0 + s;
        g_vthi[dst] = hi;
        g_vtlo[dst] = __float2bfloat16(v - __bfloat162float(hi));
    }
}

// ================= Tensor-core flash attention (pipelined) ==================
#define ATSTR 72
#define ASTG  (64 * ATSTR)
#define ATTN_SMEM (2 * 4 * ASTG * 2)     // 73728 B

__global__ __launch_bounds__(256) void attn_tc_kernel() {
    extern __shared__ __nv_bfloat16 adsm[];
    const int tid = threadIdx.x, lane = tid & 31, wid = tid >> 5;
    const int b = blockIdx.z, h = blockIdx.y, q0 = blockIdx.x * 128;
    const int bh = b * NHEAD + h;

    const __nv_bfloat16* Qh = g_qhi + (size_t)bh * S_LEN * HDIM;
    const __nv_bfloat16* Ql = g_qlo + (size_t)bh * S_LEN * HDIM;
    const __nv_bfloat16* Kh = g_khi + (size_t)bh * S_LEN * HDIM;
    const __nv_bfloat16* Kl = g_klo + (size_t)bh * S_LEN * HDIM;
    const __nv_bfloat16* Vh = g_vthi + (size_t)bh * HDIM * S_LEN;
    const __nv_bfloat16* Vl = g_vtlo + (size_t)bh * HDIM * S_LEN;

    // ---- stage Q in smem and extract fragments ----
    uint32_t qh[4][4], ql[4][4];
    {
        const uint32_t sb = smem_u32(adsm);
#pragma unroll
        for (int pass = 0; pass < 2; pass++) {
            const __nv_bfloat16* Qsrc = pass ? Ql : Qh;
#pragma unroll
            for (int i = 0; i < 2; i++) {
                int idx = tid + i * 256;
                int row = idx >> 2;
                int c16 = (idx & 3) * 16;
                *(uint4*)&adsm[row * ATSTR + c16]     = *(const uint4*)(Qsrc + (size_t)(q0 + row) * HDIM + c16);
                *(uint4*)&adsm[row * ATSTR + c16 + 8] = *(const uint4*)(Qsrc + (size_t)(q0 + row) * HDIM + c16 + 8);
            }
            __syncthreads();
#pragma unroll
            for (int ka = 0; ka < 4; ka++) {
                uint32_t a = ldsm_addr_s(sb, wid * 16, ka * 16, lane, ATSTR);
                if (pass == 0) ldsm_x4(qh[ka][0], qh[ka][1], qh[ka][2], qh[ka][3], a);
                else           ldsm_x4(ql[ka][0], ql[ka][1], ql[ka][2], ql[ka][3], a);
            }
            __syncthreads();
        }
    }

    float out[8][4];
#pragma unroll
    for (int na = 0; na < 8; na++)
#pragma unroll
        for (int r = 0; r < 4; r++) out[na][r] = 0.f;
    float m0 = -INFINITY, m1 = -INFINITY, l0 = 0.f, l1 = 0.f;

    auto stage_load = [&](int st, int t) {
        uint32_t b0 = smem_u32(adsm + st * 4 * ASTG);
#pragma unroll
        for (int i = 0; i < 2; i++) {
            int idx = tid + i * 256;
            int row = idx >> 3;
            int c8  = (idx & 7) * 8;
            uint32_t so = (uint32_t)(row * ATSTR + c8) * 2;
            size_t gk = (size_t)(t * 64 + row) * HDIM + c8;
            size_t gv = (size_t)row * S_LEN + t * 64 + c8;
            cp16(b0 + so,            Kh + gk);
            cp16(b0 + ASTG * 2 + so, Kl + gk);
            cp16(b0 + ASTG * 4 + so, Vh + gv);
            cp16(b0 + ASTG * 6 + so, Vl + gv);
        }
    };

    stage_load(0, 0);
    CP_COMMIT();

    for (int t = 0; t < S_LEN / 64; t++) {
        if (t < S_LEN / 64 - 1) stage_load((t + 1) & 1, t + 1);
        CP_COMMIT();
        CP_WAIT1();
        __syncthreads();

        uint32_t b0   = smem_u32(adsm + (t & 1) * 4 * ASTG);
        uint32_t sbKh = b0, sbKl = b0 + ASTG * 2, sbVh = b0 + ASTG * 4, sbVl = b0 + ASTG * 6;

        float sc[8][4];
#pragma unroll
        for (int na = 0; na < 8; na++)
#pragma unroll
            for (int r = 0; r < 4; r++) sc[na][r] = 0.f;

#pragma unroll
        for (int ka = 0; ka < 4; ka++) {
            uint32_t bkh[8][2], bkl[8][2];
#pragma unroll
            for (int p = 0; p < 4; p++) {
                uint32_t r0, r1, r2, r3;
                ldsm_x4(r0, r1, r2, r3, ldsm_addr_s(sbKh, p * 16, ka * 16, lane, ATSTR));
                bkh[p * 2 + 0][0] = r0; bkh[p * 2 + 0][1] = r2;
                bkh[p * 2 + 1][0] = r1; bkh[p * 2 + 1][1] = r3;
                ldsm_x4(r0, r1, r2, r3, ldsm_addr_s(sbKl, p * 16, ka * 16, lane, ATSTR));
                bkl[p * 2 + 0][0] = r0; bkl[p * 2 + 0][1] = r2;
                bkl[p * 2 + 1][0] = r1; bkl[p * 2 + 1][1] = r3;
            }
#pragma unroll
            for (int na = 0; na < 8; na++) {
                mma16816(sc[na], qh[ka], bkh[na]);
                mma16816(sc[na], qh[ka], bkl[na]);
                mma16816(sc[na], ql[ka], bkh[na]);
            }
        }

        float mt0 = -INFINITY, mt1 = -INFINITY;
#pragma unroll
        for (int na = 0; na < 8; na++) {
#pragma unroll
            for (int r = 0; r < 4; r++) sc[na][r] *= 0.125f;
            mt0 = fmaxf(mt0, fmaxf(sc[na][0], sc[na][1]));
            mt1 = fmaxf(mt1, fmaxf(sc[na][2], sc[na][3]));
        }
        mt0 = fmaxf(mt0, __shfl_xor_sync(0xffffffffu, mt0, 1));
        mt0 = fmaxf(mt0, __shfl_xor_sync(0xffffffffu, mt0, 2));
        mt1 = fmaxf(mt1, __shfl_xor_sync(0xffffffffu, mt1, 1));
        mt1 = fmaxf(mt1, __shfl_xor_sync(0xffffffffu, mt1, 2));

        float mn0 = fmaxf(m0, mt0), mn1 = fmaxf(m1, mt1);
        float al0 = __expf(m0 - mn0), al1 = __expf(m1 - mn1);
        m0 = mn0; m1 = mn1;

        uint32_t pA[8], pB[8], pAl[8], pBl[8];
        float rs0 = 0.f, rs1 = 0.f;
#pragma unroll
        for (int na = 0; na < 8; na++) {
            float p00 = __expf(sc[na][0] - m0);
            float p01 = __expf(sc[na][1] - m0);
            float p10 = __expf(sc[na][2] - m1);
            float p11 = __expf(sc[na][3] - m1);
            rs0 += p00 + p01; rs1 += p10 + p11;
            __nv_bfloat162 hv, lv;
            hv.x = __float2bfloat16(p00); hv.y = __float2bfloat16(p01);
            lv.x = __float2bfloat16(p00 - __bfloat162float(hv.x));
            lv.y = __float2bfloat16(p01 - __bfloat162float(hv.y));
            pA[na] = *(uint32_t*)&hv; pAl[na] = *(uint32_t*)&lv;
            hv.x = __float2bfloat16(p10); hv.y = __float2bfloat16(p11);
            lv.x = __float2bfloat16(p10 - __bfloat162float(hv.x));
            lv.y = __float2bfloat16(p11 - __bfloat162float(hv.y));
            pB[na] = *(uint32_t*)&hv; pBl[na] = *(uint32_t*)&lv;
        }
        rs0 += __shfl_xor_sync(0xffffffffu, rs0, 1);
        rs0 += __shfl_xor_sync(0xffffffffu, rs0, 2);
        rs1 += __shfl_xor_sync(0xffffffffu, rs1, 1);
        rs1 += __shfl_xor_sync(0xffffffffu, rs1, 2);
        l0 = l0 * al0 + rs0;
        l1 = l1 * al1 + rs1;
#pragma unroll
        for (int na = 0; na < 8; na++) {
            out[na][0] *= al0; out[na][1] *= al0;
            out[na][2] *= al1; out[na][3] *= al1;
        }

#pragma unroll
        for (int ka = 0; ka < 4; ka++) {
            uint32_t ah[4]  = {pA[2 * ka],  pB[2 * ka],  pA[2 * ka + 1],  pB[2 * ka + 1]};
            uint32_t alo[4] = {pAl[2 * ka], pBl[2 * ka], pAl[2 * ka + 1], pBl[2 * ka + 1]};
            uint32_t bvh[8][2], bvl[8][2];
#pragma unroll
            for (int p = 0; p < 4; p++) {
                uint32_t r0, r1, r2, r3;
                ldsm_x4(r0, r1, r2, r3, ldsm_addr_s(sbVh, p * 16, ka * 16, lane, ATSTR));
                bvh[p * 2 + 0][0] = r0; bvh[p * 2 + 0][1] = r2;
                bvh[p * 2 + 1][0] = r1; bvh[p * 2 + 1][1] = r3;
                ldsm_x4(r0, r1, r2, r3, ldsm_addr_s(sbVl, p * 16, ka * 16, lane, ATSTR));
                bvl[p * 2 + 0][0] = r0; bvl[p * 2 + 0][1] = r2;
                bvl[p * 2 + 1][0] = r1; bvl[p * 2 + 1][1] = r3;
            }
#pragma unroll
            for (int na = 0; na < 8; na++) {
                mma16816(out[na], ah,  bvh[na]);
                mma16816(out[na], ah,  bvl[na]);
                mma16816(out[na], alo, bvh[na]);
            }
        }
        __syncthreads();
    }

    float inv0 = 1.f / l0, inv1 = 1.f / l1;
    int gr  = lane >> 2;
    int gc2 = (lane & 3) * 2;
    int row0 = b * S_LEN + q0 + wid * 16 + gr;
#pragma unroll
    for (int na = 0; na < 8; na++) {
        int col = h * HDIM + na * 8 + gc2;
        float v0 = out[na][0] * inv0, v1 = out[na][1] * inv0;
        float v2 = out[na][2] * inv1, v3 = out[na][3] * inv1;
        __nv_bfloat162 hv, lv;
        hv.x = __float2bfloat16(v0); hv.y = __float2bfloat16(v1);
        lv.x = __float2bfloat16(v0 - __bfloat162float(hv.x));
        lv.y = __float2bfloat16(v1 - __bfloat162float(hv.y));
        *(__nv_bfloat162*)&g_ahi[(size_t)row0 * D_MODEL + col] = hv;
        *(__nv_bfloat162*)&g_alo[(size_t)row0 * D_MODEL + col] = lv;
        hv.x = __float2bfloat16(v2); hv.y = __float2bfloat16(v3);
        lv.x = __float2bfloat16(v2 - __bfloat162float(hv.x));
        lv.y = __float2bfloat16(v3 - __bfloat162float(hv.y));
        *(__nv_bfloat162*)&g_ahi[(size_t)(row0 + 8) * D_MODEL + col] = hv;
        *(__nv_bfloat162*)&g_alo[(size_t)(row0 + 8) * D_MODEL + col] = lv;
    }
}

// ================= launch =================
extern "C" void kernel_launch(void* const* d_in, const int* in_sizes, int n_in,
                              void* d_out, int out_size) {
    int xi = -1;
    for (int i = 0; i < n_in; i++)
        if (in_sizes[i] == M_ROWS * D_MODEL) { xi = i; break; }
    if (xi < 0) xi = 0;
    const float* w[4] = {0, 0, 0, 0};
    int wn = 0;
    for (int i = 0; i < n_in && wn < 4; i++)
        if (i != xi && in_sizes[i] == WSZ)
            w[wn++] = (const float*)d_in[i];

    const float* x  = (const float*)d_in[xi];
    float* out = (float*)d_out;

    cudaFuncSetAttribute(tgemm_qkv_kernel, cudaFuncAttributeMaxDynamicSharedMemorySize, GEMM_SMEM);
    cudaFuncSetAttribute(tgemm_o_kernel,   cudaFuncAttributeMaxDynamicSharedMemorySize, GEMM_SMEM);
    cudaFuncSetAttribute(attn_tc_kernel,   cudaFuncAttributeMaxDynamicSharedMemorySize, ATTN_SMEM);

    convert_x_kernel<<<(M_ROWS * D_MODEL) / 256, 256>>>(x);
    convert_w_kernel<<<(4 * WSZ) / 256, 256>>>(w[0], w[1], w[2], w[3]);

    dim3 gqkv(D_MODEL / 128, M_ROWS / 128, 3);
    tgemm_qkv_kernel<<<gqkv, 256, GEMM_SMEM>>>();

    rope_table_kernel<<<(S_LEN * 32) / 256, 256>>>();
    ropeconv_kernel<<<(M_ROWS * NHEAD * 32) / 256, 256>>>();

    dim3 gvt(S_LEN / 64, HS, 1);
    vtrans_kernel<<<gvt, 256>>>();

    dim3 gattn(S_LEN / 128, NHEAD, B_SZ);
    attn_tc_kernel<<<gattn, 256, ATTN_SMEM>>>();

    dim3 go(D_MODEL / 128, M_ROWS / 128, 1);
    tgemm_o_kernel<<<go, 256, GEMM_SMEM>>>(out);
}